// round 1
// baseline (speedup 1.0000x reference)
#include <cuda_runtime.h>

#define N_CHROM 23
#define BINS    5000
#define NB      16          // batch
#define NS      512         // samples per (c,b)
#define EOS_DIM 512
#define BIN_DIM 256
#define VOCAB   (N_CHROM * BINS)        // 115000
#define NSAMP   (N_CHROM * NB * NS)     // 188416

// ---- scratch (device globals; no allocation allowed) ----
__device__ float  g_M[3 * BIN_DIM];        // W_fc[:, :512] @ W_bin   -> [3,256]
__device__ float  g_Meos[3 * EOS_DIM];     // W_fc[:, 512:] @ W_eos   -> [3,512]
__device__ float  g_cbias[4];              // W_fc2 @ b_eos + b_fc
__device__ float4 g_E[NB * N_CHROM];       // per-(b,c) eos contribution (xyz = n0..2)
__device__ float4 g_P[VOCAB];              // per-vocab bin contribution (xyz = n0..2)

// ---------------------------------------------------------------------------
// K1: fold the weight chain. grid = 3 blocks (one per output state n), 512 thr.
// ---------------------------------------------------------------------------
__global__ void k_prep(const float* __restrict__ Wbin,   // [512,256]
                       const float* __restrict__ Weos,   // [512,512]
                       const float* __restrict__ beos,   // [512]
                       const float* __restrict__ Wfc,    // [3,1024]
                       const float* __restrict__ bfc) {  // [3]
    int n = blockIdx.x;
    int e = threadIdx.x;                 // 0..511
    __shared__ float wf[1024];
    wf[e]       = Wfc[n * 1024 + e];
    wf[e + 512] = Wfc[n * 1024 + 512 + e];
    __syncthreads();

    float acc = 0.f;
#pragma unroll 8
    for (int d = 0; d < 512; d++) acc += wf[512 + d] * Weos[d * 512 + e];
    g_Meos[n * 512 + e] = acc;

    if (e < 256) {
        float m = 0.f;
#pragma unroll 8
        for (int d = 0; d < 512; d++) m += wf[d] * Wbin[d * 256 + e];
        g_M[n * 256 + e] = m;
    }
    if (e == 0) {
        float cb = bfc[n];
        for (int d = 0; d < 512; d++) cb += wf[512 + d] * beos[d];
        g_cbias[n] = cb;
    }
}

// ---------------------------------------------------------------------------
// K2a: E[b,c,n] = eos_emb[b,c,:] . Meos[n,:] + cbias[n].  One warp per (b,c).
// ---------------------------------------------------------------------------
__global__ void k_eos(const float* __restrict__ eos_emb) {   // [B, C, 512]
    int w    = (blockIdx.x * blockDim.x + threadIdx.x) >> 5;  // 0..367 = b*23+c
    int lane = threadIdx.x & 31;
    if (w >= NB * N_CHROM) return;
    const float* row = eos_emb + (size_t)w * EOS_DIM;
    float s0 = 0.f, s1 = 0.f, s2 = 0.f;
#pragma unroll 4
    for (int i = lane; i < EOS_DIM; i += 32) {
        float x = row[i];
        s0 += x * g_Meos[i];
        s1 += x * g_Meos[EOS_DIM + i];
        s2 += x * g_Meos[2 * EOS_DIM + i];
    }
#pragma unroll
    for (int o = 16; o; o >>= 1) {
        s0 += __shfl_down_sync(0xffffffffu, s0, o);
        s1 += __shfl_down_sync(0xffffffffu, s1, o);
        s2 += __shfl_down_sync(0xffffffffu, s2, o);
    }
    if (lane == 0)
        g_E[w] = make_float4(s0 + g_cbias[0], s1 + g_cbias[1], s2 + g_cbias[2], 0.f);
}

// ---------------------------------------------------------------------------
// K2b: P[v,n] = table[v,:] . M[n,:].  One warp per vocab row; streams the
// 117.8 MB table exactly once, fully coalesced float4. HBM-bound.
// ---------------------------------------------------------------------------
__global__ void k_table(const float4* __restrict__ tbl) {    // [VOCAB, 64] float4
    __shared__ float4 sM[3 * 64];
    int t = threadIdx.x;
    if (t < 192) sM[t] = reinterpret_cast<const float4*>(g_M)[t];
    __syncthreads();

    int v    = (blockIdx.x * blockDim.x + t) >> 5;
    int lane = t & 31;
    if (v >= VOCAB) return;

    float4 a = tbl[(size_t)v * 64 + lane];        // bytes [0,512) of the row
    float4 b = tbl[(size_t)v * 64 + 32 + lane];   // bytes [512,1024)

    float s0, s1, s2;
    {
        float4 m = sM[lane], mb = sM[32 + lane];
        s0 = a.x*m.x + a.y*m.y + a.z*m.z + a.w*m.w
           + b.x*mb.x + b.y*mb.y + b.z*mb.z + b.w*mb.w;
    }
    {
        float4 m = sM[64 + lane], mb = sM[96 + lane];
        s1 = a.x*m.x + a.y*m.y + a.z*m.z + a.w*m.w
           + b.x*mb.x + b.y*mb.y + b.z*mb.z + b.w*mb.w;
    }
    {
        float4 m = sM[128 + lane], mb = sM[160 + lane];
        s2 = a.x*m.x + a.y*m.y + a.z*m.z + a.w*m.w
           + b.x*mb.x + b.y*mb.y + b.z*mb.z + b.w*mb.w;
    }
#pragma unroll
    for (int o = 16; o; o >>= 1) {
        s0 += __shfl_down_sync(0xffffffffu, s0, o);
        s1 += __shfl_down_sync(0xffffffffu, s1, o);
        s2 += __shfl_down_sync(0xffffffffu, s2, o);
    }
    if (lane == 0) g_P[v] = make_float4(s0, s1, s2, 0.f);
}

// ---------------------------------------------------------------------------
// K3: pred[c,b,s,:] = relu(P[c*5000 + sampled[c,b,s]] + E[b,c]); emit targets.
// One thread per sample.
// ---------------------------------------------------------------------------
__global__ void k_out(const int* __restrict__ sampled,
                      const int* __restrict__ targets,
                      float* __restrict__ out,
                      int write_targets) {
    int i = blockIdx.x * blockDim.x + threadIdx.x;
    if (i >= NSAMP) return;
    int c  = i / (NB * NS);
    int bs = i - c * (NB * NS);
    int b  = bs / NS;

    int    v = c * BINS + sampled[i];
    float4 p = g_P[v];
    float4 e = g_E[b * N_CHROM + c];

    float r0 = fmaxf(p.x + e.x, 0.f);
    float r1 = fmaxf(p.y + e.y, 0.f);
    float r2 = fmaxf(p.z + e.z, 0.f);

    out[3 * i + 0] = r0;
    out[3 * i + 1] = r1;
    out[3 * i + 2] = r2;
    if (write_targets) out[3 * NSAMP + i] = (float)targets[i];
}

// ---------------------------------------------------------------------------
extern "C" void kernel_launch(void* const* d_in, const int* in_sizes, int n_in,
                              void* d_out, int out_size) {
    const float*  eos_emb = (const float*) d_in[0];  // [16,23,512]
    const int*    sampled = (const int*)   d_in[1];  // [23,16,512]
    const int*    targets = (const int*)   d_in[2];  // [23,16,512]
    const float4* tbl     = (const float4*)d_in[3];  // [115000,256] f32
    const float*  Wbin    = (const float*) d_in[4];  // [512,256]
    const float*  Weos    = (const float*) d_in[5];  // [512,512]
    const float*  beos    = (const float*) d_in[6];  // [512]
    const float*  Wfc     = (const float*) d_in[7];  // [3,1024]
    const float*  bfc     = (const float*) d_in[8];  // [3]
    float* out = (float*)d_out;

    k_prep<<<3, 512>>>(Wbin, Weos, beos, Wfc, bfc);
    k_eos<<<(NB * N_CHROM * 32 + 255) / 256, 256>>>(eos_emb);
    k_table<<<(VOCAB * 32 + 255) / 256, 256>>>(tbl);

    int write_targets = (out_size >= 4 * NSAMP) ? 1 : 0;
    k_out<<<(NSAMP + 255) / 256, 256>>>(sampled, targets, out, write_targets);
}

// round 2
// speedup vs baseline: 2.7417x; 2.7417x over previous
#include <cuda_runtime.h>

#define N_CHROM 23
#define BINS    5000
#define NB      16
#define NS      512
#define EOS_DIM 512
#define BIN_DIM 256
#define VOCAB   (N_CHROM * BINS)        // 115000
#define NSAMP   (N_CHROM * NB * NS)     // 188416

// ---- scratch (device globals) ----
__device__ float  g_M[3 * BIN_DIM];        // W_fc[:, :512] @ W_bin   -> [3,256]
__device__ float  g_Meos[3 * EOS_DIM];     // W_fc[:, 512:] @ W_eos   -> [3,512]
__device__ float  g_cbias[4];              // W_fc2 @ b_eos + b_fc
__device__ float4 g_E[NB * N_CHROM];       // per-(b,c) eos contribution
__device__ float4 g_P[VOCAB];              // per-vocab bin contribution

// ---------------------------------------------------------------------------
// K1: fold the weight chain, now fully parallel.
//   blocks 0..15 : g_Meos columns  (32 e each, d-loop split over 16 warps)
//   blocks 16..23: g_M columns     (32 e each)
//   block  24    : g_cbias (one warp)
// 512 threads/block.
// ---------------------------------------------------------------------------
__global__ void k_prep(const float* __restrict__ Wbin,   // [512,256]
                       const float* __restrict__ Weos,   // [512,512]
                       const float* __restrict__ beos,   // [512]
                       const float* __restrict__ Wfc,    // [3,1024]
                       const float* __restrict__ bfc) {  // [3]
    int blk  = blockIdx.x;
    int lane = threadIdx.x & 31;
    int dg   = threadIdx.x >> 5;           // 0..15 d-groups

    __shared__ float s[3][16][32];

    if (blk < 24) {
        bool is_eos = (blk < 16);
        int  e0     = is_eos ? blk * 32 : (blk - 16) * 32;
        int  e      = e0 + lane;
        int  stride = is_eos ? 512 : 256;
        const float* W     = is_eos ? Weos : Wbin;
        int  fc_off = is_eos ? 512 : 0;     // second vs first half of W_fc row

        float a0 = 0.f, a1 = 0.f, a2 = 0.f;
        int dbeg = dg * 32;
#pragma unroll 8
        for (int d = dbeg; d < dbeg + 32; d++) {
            float w = W[d * stride + e];
            a0 += __ldg(&Wfc[fc_off + d])        * w;
            a1 += __ldg(&Wfc[1024 + fc_off + d]) * w;
            a2 += __ldg(&Wfc[2048 + fc_off + d]) * w;
        }
        s[0][dg][lane] = a0;
        s[1][dg][lane] = a1;
        s[2][dg][lane] = a2;
        __syncthreads();
#pragma unroll
        for (int off = 8; off; off >>= 1) {
            if (dg < off) {
                s[0][dg][lane] += s[0][dg + off][lane];
                s[1][dg][lane] += s[1][dg + off][lane];
                s[2][dg][lane] += s[2][dg + off][lane];
            }
            __syncthreads();
        }
        if (dg == 0) {
            if (is_eos) {
                g_Meos[e]             = s[0][0][lane];
                g_Meos[512 + e]       = s[1][0][lane];
                g_Meos[1024 + e]      = s[2][0][lane];
            } else {
                g_M[e]                = s[0][0][lane];
                g_M[256 + e]          = s[1][0][lane];
                g_M[512 + e]          = s[2][0][lane];
            }
        }
    } else if (threadIdx.x < 32) {
        // cbias: one warp, 16 d's per lane
        float a0 = 0.f, a1 = 0.f, a2 = 0.f;
#pragma unroll
        for (int d = lane; d < 512; d += 32) {
            float v = beos[d];
            a0 += Wfc[512 + d]        * v;
            a1 += Wfc[1024 + 512 + d] * v;
            a2 += Wfc[2048 + 512 + d] * v;
        }
#pragma unroll
        for (int o = 16; o; o >>= 1) {
            a0 += __shfl_down_sync(0xffffffffu, a0, o);
            a1 += __shfl_down_sync(0xffffffffu, a1, o);
            a2 += __shfl_down_sync(0xffffffffu, a2, o);
        }
        if (lane == 0) {
            g_cbias[0] = a0 + bfc[0];
            g_cbias[1] = a1 + bfc[1];
            g_cbias[2] = a2 + bfc[2];
        }
    }
}

// ---------------------------------------------------------------------------
// K2a: E[b,c,n] = eos_emb[b,c,:] . Meos[n,:] + cbias[n].  One warp per (b,c).
// ---------------------------------------------------------------------------
__global__ void k_eos(const float* __restrict__ eos_emb) {   // [B, C, 512]
    int w    = (blockIdx.x * blockDim.x + threadIdx.x) >> 5;
    int lane = threadIdx.x & 31;
    if (w >= NB * N_CHROM) return;
    const float4* row = reinterpret_cast<const float4*>(eos_emb + (size_t)w * EOS_DIM);
    const float4* M0  = reinterpret_cast<const float4*>(g_Meos);
    const float4* M1  = reinterpret_cast<const float4*>(g_Meos + EOS_DIM);
    const float4* M2  = reinterpret_cast<const float4*>(g_Meos + 2 * EOS_DIM);
    float s0 = 0.f, s1 = 0.f, s2 = 0.f;
#pragma unroll
    for (int i = lane; i < EOS_DIM / 4; i += 32) {
        float4 x = row[i];
        float4 m0 = M0[i], m1 = M1[i], m2 = M2[i];
        s0 += x.x*m0.x + x.y*m0.y + x.z*m0.z + x.w*m0.w;
        s1 += x.x*m1.x + x.y*m1.y + x.z*m1.z + x.w*m1.w;
        s2 += x.x*m2.x + x.y*m2.y + x.z*m2.z + x.w*m2.w;
    }
#pragma unroll
    for (int o = 16; o; o >>= 1) {
        s0 += __shfl_down_sync(0xffffffffu, s0, o);
        s1 += __shfl_down_sync(0xffffffffu, s1, o);
        s2 += __shfl_down_sync(0xffffffffu, s2, o);
    }
    if (lane == 0)
        g_E[w] = make_float4(s0 + g_cbias[0], s1 + g_cbias[1], s2 + g_cbias[2], 0.f);
}

// ---------------------------------------------------------------------------
// K2b: P[v,n] = table[v,:] . M[n,:].  One warp per vocab row; streams the
// 117.8 MB table exactly once, coalesced float4. HBM-bound.
// ---------------------------------------------------------------------------
__global__ void k_table(const float4* __restrict__ tbl) {    // [VOCAB, 64] float4
    __shared__ float4 sM[3 * 64];
    int t = threadIdx.x;
    if (t < 192) sM[t] = reinterpret_cast<const float4*>(g_M)[t];
    __syncthreads();

    int v    = (blockIdx.x * blockDim.x + t) >> 5;
    int lane = t & 31;
    if (v >= VOCAB) return;

    float4 a = tbl[(size_t)v * 64 + lane];
    float4 b = tbl[(size_t)v * 64 + 32 + lane];

    float s0, s1, s2;
    {
        float4 m = sM[lane], mb = sM[32 + lane];
        s0 = a.x*m.x + a.y*m.y + a.z*m.z + a.w*m.w
           + b.x*mb.x + b.y*mb.y + b.z*mb.z + b.w*mb.w;
    }
    {
        float4 m = sM[64 + lane], mb = sM[96 + lane];
        s1 = a.x*m.x + a.y*m.y + a.z*m.z + a.w*m.w
           + b.x*mb.x + b.y*mb.y + b.z*mb.z + b.w*mb.w;
    }
    {
        float4 m = sM[128 + lane], mb = sM[160 + lane];
        s2 = a.x*m.x + a.y*m.y + a.z*m.z + a.w*m.w
           + b.x*mb.x + b.y*mb.y + b.z*mb.z + b.w*mb.w;
    }
#pragma unroll
    for (int o = 16; o; o >>= 1) {
        s0 += __shfl_down_sync(0xffffffffu, s0, o);
        s1 += __shfl_down_sync(0xffffffffu, s1, o);
        s2 += __shfl_down_sync(0xffffffffu, s2, o);
    }
    if (lane == 0) g_P[v] = make_float4(s0, s1, s2, 0.f);
}

// ---------------------------------------------------------------------------
// K3: 4 samples per thread; all vector loads/stores.
// NS=512 divisible by 4 => 4 consecutive samples share (c,b).
// ---------------------------------------------------------------------------
__global__ void k_out(const int4* __restrict__ sampled,
                      const int4* __restrict__ targets,
                      float* __restrict__ out,
                      int write_targets) {
    int q = blockIdx.x * blockDim.x + threadIdx.x;     // quad index
    if (q >= NSAMP / 4) return;
    int i  = q * 4;
    int c  = i / (NB * NS);
    int b  = (i - c * (NB * NS)) / NS;

    int4 sv = sampled[q];
    int  vb = c * BINS;
    float4 p0 = g_P[vb + sv.x];
    float4 p1 = g_P[vb + sv.y];
    float4 p2 = g_P[vb + sv.z];
    float4 p3 = g_P[vb + sv.w];
    float4 e  = g_E[b * N_CHROM + c];

    float r[12];
    r[0]  = fmaxf(p0.x + e.x, 0.f); r[1]  = fmaxf(p0.y + e.y, 0.f); r[2]  = fmaxf(p0.z + e.z, 0.f);
    r[3]  = fmaxf(p1.x + e.x, 0.f); r[4]  = fmaxf(p1.y + e.y, 0.f); r[5]  = fmaxf(p1.z + e.z, 0.f);
    r[6]  = fmaxf(p2.x + e.x, 0.f); r[7]  = fmaxf(p2.y + e.y, 0.f); r[8]  = fmaxf(p2.z + e.z, 0.f);
    r[9]  = fmaxf(p3.x + e.x, 0.f); r[10] = fmaxf(p3.y + e.y, 0.f); r[11] = fmaxf(p3.z + e.z, 0.f);

    float4* o4 = reinterpret_cast<float4*>(out + 12 * (size_t)q);
    o4[0] = make_float4(r[0], r[1], r[2],  r[3]);
    o4[1] = make_float4(r[4], r[5], r[6],  r[7]);
    o4[2] = make_float4(r[8], r[9], r[10], r[11]);

    if (write_targets) {
        int4 tv = targets[q];
        reinterpret_cast<float4*>(out + 3 * NSAMP)[q] =
            make_float4((float)tv.x, (float)tv.y, (float)tv.z, (float)tv.w);
    }
}

// ---------------------------------------------------------------------------
extern "C" void kernel_launch(void* const* d_in, const int* in_sizes, int n_in,
                              void* d_out, int out_size) {
    const float*  eos_emb = (const float*) d_in[0];
    const int4*   sampled = (const int4*)  d_in[1];
    const int4*   targets = (const int4*)  d_in[2];
    const float4* tbl     = (const float4*)d_in[3];
    const float*  Wbin    = (const float*) d_in[4];
    const float*  Weos    = (const float*) d_in[5];
    const float*  beos    = (const float*) d_in[6];
    const float*  Wfc     = (const float*) d_in[7];
    const float*  bfc     = (const float*) d_in[8];
    float* out = (float*)d_out;

    k_prep<<<25, 512>>>(Wbin, Weos, beos, Wfc, bfc);
    k_table<<<(VOCAB * 32 + 255) / 256, 256>>>(tbl);
    k_eos<<<(NB * N_CHROM * 32 + 255) / 256, 256>>>(eos_emb);

    int write_targets = (out_size >= 4 * NSAMP) ? 1 : 0;
    k_out<<<(NSAMP / 4 + 255) / 256, 256>>>(sampled, targets, out, write_targets);
}

// round 3
// speedup vs baseline: 3.9580x; 1.4436x over previous
#include <cuda_runtime.h>

#define N_CHROM 23
#define BINS    5000
#define NB      16
#define NS      512
#define EOS_DIM 512
#define BIN_DIM 256
#define VOCAB   (N_CHROM * BINS)        // 115000
#define NSAMP   (N_CHROM * NB * NS)     // 188416
#define GRID    592                     // 148 SMs * 4 resident blocks
#define NWARPS  (GRID * 8)              // 4736

// ---- scratch (device globals) ----
__device__ float    g_M[3 * BIN_DIM];      // W_fc[:, :512] @ W_bin   -> [3,256]
__device__ float    g_Meos[3 * EOS_DIM];   // W_fc[:, 512:] @ W_eos   -> [3,512]
__device__ float    g_cbias[4];            // W_fc2 @ b_eos + b_fc
__device__ float4   g_E[NB * N_CHROM];     // per-(b,c) eos contribution
__device__ float4   g_P[VOCAB];            // per-vocab bin contribution
__device__ unsigned g_bar;                 // monotone barrier counter (zero-init)

// Software grid barrier: monotone counter, absolute target. All GRID blocks
// are co-resident (grid == exact residency), so spinning is deadlock-free.
__device__ __forceinline__ void grid_bar(unsigned target) {
    __syncthreads();
    if (threadIdx.x == 0) {
        __threadfence();                               // release my writes
        unsigned prev = atomicAdd(&g_bar, 1u);
        if (prev + 1u < target) {
            while (*(volatile unsigned*)&g_bar < target) __nanosleep(64);
        }
        __threadfence();                               // acquire + L1 invalidate
    }
    __syncthreads();
}

__global__ void __launch_bounds__(256, 4)
k_fused(const float*  __restrict__ eos_emb,   // [16,23,512]
        const int4*   __restrict__ sampled,   // [23,16,512] as quads
        const int4*   __restrict__ targets,
        const float4* __restrict__ tbl,       // [115000,64] float4
        const float*  __restrict__ Wbin,      // [512,256]
        const float*  __restrict__ Weos,      // [512,512]
        const float*  __restrict__ beos,      // [512]
        const float*  __restrict__ Wfc,       // [3,1024]
        const float*  __restrict__ bfc,       // [3]
        float* __restrict__ out,
        int write_targets) {
    const int bid  = blockIdx.x;
    const int tid  = threadIdx.x;
    const int lane = tid & 31;
    const int warp = tid >> 5;

    __shared__ float  s[3][8][32];
    __shared__ float4 sM[3 * 64];

    // ================= Phase 0: fold the weight chain =================
    if (bid < 24) {
        bool is_eos = (bid < 16);
        int  e      = (is_eos ? bid * 32 : (bid - 16) * 32) + lane;
        int  stride = is_eos ? 512 : 256;
        const float* W = is_eos ? Weos : Wbin;
        int  fc     = is_eos ? 512 : 0;

        float a0 = 0.f, a1 = 0.f, a2 = 0.f;
        int dbeg = warp * 64;
#pragma unroll 8
        for (int d = dbeg; d < dbeg + 64; d++) {
            float w = W[d * stride + e];
            a0 += __ldg(&Wfc[fc + d])        * w;
            a1 += __ldg(&Wfc[1024 + fc + d]) * w;
            a2 += __ldg(&Wfc[2048 + fc + d]) * w;
        }
        s[0][warp][lane] = a0;
        s[1][warp][lane] = a1;
        s[2][warp][lane] = a2;
        __syncthreads();
#pragma unroll
        for (int off = 4; off; off >>= 1) {
            if (warp < off) {
                s[0][warp][lane] += s[0][warp + off][lane];
                s[1][warp][lane] += s[1][warp + off][lane];
                s[2][warp][lane] += s[2][warp + off][lane];
            }
            __syncthreads();
        }
        if (warp == 0) {
            if (is_eos) {
                g_Meos[e]        = s[0][0][lane];
                g_Meos[512 + e]  = s[1][0][lane];
                g_Meos[1024 + e] = s[2][0][lane];
            } else {
                g_M[e]           = s[0][0][lane];
                g_M[256 + e]     = s[1][0][lane];
                g_M[512 + e]     = s[2][0][lane];
            }
        }
    } else if (bid == 24 && tid < 32) {
        float a0 = 0.f, a1 = 0.f, a2 = 0.f;
#pragma unroll
        for (int d = lane; d < 512; d += 32) {
            float v = beos[d];
            a0 += Wfc[512 + d]        * v;
            a1 += Wfc[1024 + 512 + d] * v;
            a2 += Wfc[2048 + 512 + d] * v;
        }
#pragma unroll
        for (int o = 16; o; o >>= 1) {
            a0 += __shfl_down_sync(0xffffffffu, a0, o);
            a1 += __shfl_down_sync(0xffffffffu, a1, o);
            a2 += __shfl_down_sync(0xffffffffu, a2, o);
        }
        if (lane == 0) {
            g_cbias[0] = a0 + bfc[0];
            g_cbias[1] = a1 + bfc[1];
            g_cbias[2] = a2 + bfc[2];
        }
    }

    grid_bar(GRID);   // ---- barrier A: g_M / g_Meos / g_cbias ready ----

    // stage folded bin matrix into smem for the table sweep
    if (tid < 192) sM[tid] = reinterpret_cast<const float4*>(g_M)[tid];
    __syncthreads();

    // ================= Phase 1a: eos dot (368 warps) =================
    if (bid < 46) {
        int w = bid * 8 + warp;   // 0..367 = b*23 + c
        const float4* row = reinterpret_cast<const float4*>(eos_emb + (size_t)w * EOS_DIM);
        const float4* M0  = reinterpret_cast<const float4*>(g_Meos);
        const float4* M1  = reinterpret_cast<const float4*>(g_Meos + EOS_DIM);
        const float4* M2  = reinterpret_cast<const float4*>(g_Meos + 2 * EOS_DIM);
        float s0 = 0.f, s1 = 0.f, s2 = 0.f;
#pragma unroll
        for (int i = lane; i < EOS_DIM / 4; i += 32) {
            float4 x = row[i];
            float4 m0 = M0[i], m1 = M1[i], m2 = M2[i];
            s0 += x.x*m0.x + x.y*m0.y + x.z*m0.z + x.w*m0.w;
            s1 += x.x*m1.x + x.y*m1.y + x.z*m1.z + x.w*m1.w;
            s2 += x.x*m2.x + x.y*m2.y + x.z*m2.z + x.w*m2.w;
        }
#pragma unroll
        for (int o = 16; o; o >>= 1) {
            s0 += __shfl_down_sync(0xffffffffu, s0, o);
            s1 += __shfl_down_sync(0xffffffffu, s1, o);
            s2 += __shfl_down_sync(0xffffffffu, s2, o);
        }
        if (lane == 0)
            g_E[w] = make_float4(s0 + g_cbias[0], s1 + g_cbias[1], s2 + g_cbias[2], 0.f);
    }

    // ================= Phase 1b: table sweep (2 rows / warp-iter) =====
    {
        int gw = bid * 8 + warp;                    // 0..4735
        for (int p = gw; p < VOCAB / 2; p += NWARPS) {
            size_t base = (size_t)p * 128;          // two 64-float4 rows
            float4 a0 = __ldcs(&tbl[base + lane]);
            float4 b0 = __ldcs(&tbl[base + 32 + lane]);
            float4 a1 = __ldcs(&tbl[base + 64 + lane]);
            float4 b1 = __ldcs(&tbl[base + 96 + lane]);

            float r0, r1, r2, t0, t1, t2;
            {
                float4 m = sM[lane], mb = sM[32 + lane];
                r0 = a0.x*m.x + a0.y*m.y + a0.z*m.z + a0.w*m.w
                   + b0.x*mb.x + b0.y*mb.y + b0.z*mb.z + b0.w*mb.w;
                t0 = a1.x*m.x + a1.y*m.y + a1.z*m.z + a1.w*m.w
                   + b1.x*mb.x + b1.y*mb.y + b1.z*mb.z + b1.w*mb.w;
            }
            {
                float4 m = sM[64 + lane], mb = sM[96 + lane];
                r1 = a0.x*m.x + a0.y*m.y + a0.z*m.z + a0.w*m.w
                   + b0.x*mb.x + b0.y*mb.y + b0.z*mb.z + b0.w*mb.w;
                t1 = a1.x*m.x + a1.y*m.y + a1.z*m.z + a1.w*m.w
                   + b1.x*mb.x + b1.y*mb.y + b1.z*mb.z + b1.w*mb.w;
            }
            {
                float4 m = sM[128 + lane], mb = sM[160 + lane];
                r2 = a0.x*m.x + a0.y*m.y + a0.z*m.z + a0.w*m.w
                   + b0.x*mb.x + b0.y*mb.y + b0.z*mb.z + b0.w*mb.w;
                t2 = a1.x*m.x + a1.y*m.y + a1.z*m.z + a1.w*m.w
                   + b1.x*mb.x + b1.y*mb.y + b1.z*mb.z + b1.w*mb.w;
            }
#pragma unroll
            for (int o = 16; o; o >>= 1) {
                r0 += __shfl_xor_sync(0xffffffffu, r0, o);
                r1 += __shfl_xor_sync(0xffffffffu, r1, o);
                r2 += __shfl_xor_sync(0xffffffffu, r2, o);
                t0 += __shfl_xor_sync(0xffffffffu, t0, o);
                t1 += __shfl_xor_sync(0xffffffffu, t1, o);
                t2 += __shfl_xor_sync(0xffffffffu, t2, o);
            }
            if (lane == 0) {
                g_P[2 * p]     = make_float4(r0, r1, r2, 0.f);
                g_P[2 * p + 1] = make_float4(t0, t1, t2, 0.f);
            }
        }
    }

    grid_bar(2 * GRID);   // ---- barrier B: g_P / g_E ready ----

    // ================= Phase 2: gather + relu + emit ==================
    {
        int q = bid * 80 + tid;                 // 80 quads/block, coalesced
        if (tid < 80 && q < NSAMP / 4) {
            int i = q * 4;
            int c = i / (NB * NS);
            int b = (i - c * (NB * NS)) / NS;

            int4 sv = sampled[q];
            int  vb = c * BINS;
            float4 p0 = g_P[vb + sv.x];
            float4 p1 = g_P[vb + sv.y];
            float4 p2 = g_P[vb + sv.z];
            float4 p3 = g_P[vb + sv.w];
            float4 e  = g_E[b * N_CHROM + c];

            float4* o4 = reinterpret_cast<float4*>(out + 12 * (size_t)q);
            o4[0] = make_float4(fmaxf(p0.x + e.x, 0.f), fmaxf(p0.y + e.y, 0.f),
                                fmaxf(p0.z + e.z, 0.f), fmaxf(p1.x + e.x, 0.f));
            o4[1] = make_float4(fmaxf(p1.y + e.y, 0.f), fmaxf(p1.z + e.z, 0.f),
                                fmaxf(p2.x + e.x, 0.f), fmaxf(p2.y + e.y, 0.f));
            o4[2] = make_float4(fmaxf(p2.z + e.z, 0.f), fmaxf(p3.x + e.x, 0.f),
                                fmaxf(p3.y + e.y, 0.f), fmaxf(p3.z + e.z, 0.f));

            if (write_targets) {
                int4 tv = targets[q];
                reinterpret_cast<float4*>(out + 3 * NSAMP)[q] =
                    make_float4((float)tv.x, (float)tv.y, (float)tv.z, (float)tv.w);
            }
        }
    }

    // ---- final arrive: 1776th arrival resets the counter for replay ----
    __syncthreads();
    if (tid == 0) {
        unsigned prev = atomicAdd(&g_bar, 1u);
        if (prev + 1u == 3u * GRID) atomicExch(&g_bar, 0u);
    }
}

// ---------------------------------------------------------------------------
extern "C" void kernel_launch(void* const* d_in, const int* in_sizes, int n_in,
                              void* d_out, int out_size) {
    const float*  eos_emb = (const float*) d_in[0];
    const int4*   sampled = (const int4*)  d_in[1];
    const int4*   targets = (const int4*)  d_in[2];
    const float4* tbl     = (const float4*)d_in[3];
    const float*  Wbin    = (const float*) d_in[4];
    const float*  Weos    = (const float*) d_in[5];
    const float*  beos    = (const float*) d_in[6];
    const float*  Wfc     = (const float*) d_in[7];
    const float*  bfc     = (const float*) d_in[8];
    float* out = (float*)d_out;

    int write_targets = (out_size >= 4 * NSAMP) ? 1 : 0;
    k_fused<<<GRID, 256>>>(eos_emb, sampled, targets, tbl,
                           Wbin, Weos, beos, Wfc, bfc, out, write_targets);
}

// round 4
// speedup vs baseline: 3.9621x; 1.0010x over previous
#include <cuda_runtime.h>

#define N_CHROM 23
#define BINS    5000
#define NB      16
#define NS      512
#define EOS_DIM 512
#define BIN_DIM 256
#define VOCAB   (N_CHROM * BINS)        // 115000
#define NSAMP   (N_CHROM * NB * NS)     // 188416
#define GRID    592                     // 148 SMs * 4 resident blocks
#define NWARPS  (GRID * 8)              // 4736
#define NUNITS  (VOCAB / 2)             // 57500 two-row units
#define EOS_B0  (GRID - 46)             // eos handled by high block ids

// ---- scratch (device globals) ----
__device__ float    g_M[3 * BIN_DIM];      // W_fc[:, :512] @ W_bin   -> [3,256]
__device__ float    g_Meos[3 * EOS_DIM];   // W_fc[:, 512:] @ W_eos   -> [3,512]
__device__ float    g_cbias[4];            // W_fc2 @ b_eos + b_fc
__device__ float4   g_E[NB * N_CHROM];     // per-(b,c) eos contribution
__device__ float4   g_P[VOCAB];            // per-vocab bin contribution
__device__ unsigned g_bar;                 // monotone barrier counter (zero-init)

__device__ __forceinline__ void grid_bar(unsigned target) {
    __syncthreads();
    if (threadIdx.x == 0) {
        __threadfence();
        unsigned prev = atomicAdd(&g_bar, 1u);
        if (prev + 1u < target) {
            while (*(volatile unsigned*)&g_bar < target) __nanosleep(32);
        }
        __threadfence();
    }
    __syncthreads();
}

__device__ __forceinline__ float dot8(float4 a, float4 b, float4 m, float4 mb) {
    return a.x*m.x + a.y*m.y + a.z*m.z + a.w*m.w
         + b.x*mb.x + b.y*mb.y + b.z*mb.z + b.w*mb.w;
}

__global__ void __launch_bounds__(256, 4)
k_fused(const float*  __restrict__ eos_emb,   // [16,23,512]
        const int4*   __restrict__ sampled,   // [23,16,512] as quads
        const int4*   __restrict__ targets,
        const float4* __restrict__ tbl,       // [115000,64] float4
        const float*  __restrict__ Wbin,      // [512,256]
        const float*  __restrict__ Weos,      // [512,512]
        const float*  __restrict__ beos,      // [512]
        const float*  __restrict__ Wfc,       // [3,1024]
        const float*  __restrict__ bfc,       // [3]
        float* __restrict__ out,
        int write_targets) {
    const int bid  = blockIdx.x;
    const int tid  = threadIdx.x;
    const int lane = tid & 31;
    const int warp = tid >> 5;

    __shared__ float  s[3][8][32];
    __shared__ float4 sM[3 * 64];

    // ================= Phase 0: fold the weight chain =================
    if (bid < 24) {
        bool is_eos = (bid < 16);
        int  e      = (is_eos ? bid * 32 : (bid - 16) * 32) + lane;
        int  stride = is_eos ? 512 : 256;
        const float* W = is_eos ? Weos : Wbin;
        int  fc     = is_eos ? 512 : 0;

        float a0 = 0.f, a1 = 0.f, a2 = 0.f;
        int dbeg = warp * 64;
#pragma unroll 16
        for (int d = dbeg; d < dbeg + 64; d++) {
            float w = W[d * stride + e];
            a0 += __ldg(&Wfc[fc + d])        * w;
            a1 += __ldg(&Wfc[1024 + fc + d]) * w;
            a2 += __ldg(&Wfc[2048 + fc + d]) * w;
        }
        s[0][warp][lane] = a0;
        s[1][warp][lane] = a1;
        s[2][warp][lane] = a2;
        __syncthreads();
#pragma unroll
        for (int off = 4; off; off >>= 1) {
            if (warp < off) {
                s[0][warp][lane] += s[0][warp + off][lane];
                s[1][warp][lane] += s[1][warp + off][lane];
                s[2][warp][lane] += s[2][warp + off][lane];
            }
            __syncthreads();
        }
        if (warp == 0) {
            if (is_eos) {
                g_Meos[e]        = s[0][0][lane];
                g_Meos[512 + e]  = s[1][0][lane];
                g_Meos[1024 + e] = s[2][0][lane];
            } else {
                g_M[e]           = s[0][0][lane];
                g_M[256 + e]     = s[1][0][lane];
                g_M[512 + e]     = s[2][0][lane];
            }
        }
    } else if (bid == 24 && tid < 32) {
        float a0 = 0.f, a1 = 0.f, a2 = 0.f;
#pragma unroll
        for (int d = lane; d < 512; d += 32) {
            float v = beos[d];
            a0 += Wfc[512 + d]        * v;
            a1 += Wfc[1024 + 512 + d] * v;
            a2 += Wfc[2048 + 512 + d] * v;
        }
#pragma unroll
        for (int o = 16; o; o >>= 1) {
            a0 += __shfl_down_sync(0xffffffffu, a0, o);
            a1 += __shfl_down_sync(0xffffffffu, a1, o);
            a2 += __shfl_down_sync(0xffffffffu, a2, o);
        }
        if (lane == 0) {
            g_cbias[0] = a0 + bfc[0];
            g_cbias[1] = a1 + bfc[1];
            g_cbias[2] = a2 + bfc[2];
        }
    }

    grid_bar(GRID);   // ---- barrier A: g_M / g_Meos / g_cbias ready ----

    if (tid < 192) sM[tid] = reinterpret_cast<const float4*>(g_M)[tid];
    __syncthreads();

    // ================= Phase 1a: eos dot (high blocks) =================
    if (bid >= EOS_B0) {
        int w = (bid - EOS_B0) * 8 + warp;   // 0..367 = b*23 + c
        const float4* row = reinterpret_cast<const float4*>(eos_emb + (size_t)w * EOS_DIM);
        const float4* M0  = reinterpret_cast<const float4*>(g_Meos);
        const float4* M1  = reinterpret_cast<const float4*>(g_Meos + EOS_DIM);
        const float4* M2  = reinterpret_cast<const float4*>(g_Meos + 2 * EOS_DIM);
        float s0 = 0.f, s1 = 0.f, s2 = 0.f;
#pragma unroll
        for (int i = lane; i < EOS_DIM / 4; i += 32) {
            float4 x = row[i];
            float4 m0 = M0[i], m1 = M1[i], m2 = M2[i];
            s0 += x.x*m0.x + x.y*m0.y + x.z*m0.z + x.w*m0.w;
            s1 += x.x*m1.x + x.y*m1.y + x.z*m1.z + x.w*m1.w;
            s2 += x.x*m2.x + x.y*m2.y + x.z*m2.z + x.w*m2.w;
        }
#pragma unroll
        for (int o = 16; o; o >>= 1) {
            s0 += __shfl_down_sync(0xffffffffu, s0, o);
            s1 += __shfl_down_sync(0xffffffffu, s1, o);
            s2 += __shfl_down_sync(0xffffffffu, s2, o);
        }
        if (lane == 0)
            g_E[w] = make_float4(s0 + g_cbias[0], s1 + g_cbias[1], s2 + g_cbias[2], 0.f);
    }

    // ===== Phase 1b: table sweep, software-pipelined (2 rows / unit) =====
    {
        const int gw = bid * 8 + warp;                // 0..4735, always < NUNITS
        int p = gw;

        float4 A0, A1, A2, A3;
        {
            const float4* b0 = tbl + (size_t)p * 128;
            A0 = __ldcs(b0 + lane);
            A1 = __ldcs(b0 + 32 + lane);
            A2 = __ldcs(b0 + 64 + lane);
            A3 = __ldcs(b0 + 96 + lane);
        }
        while (true) {
            int  pn   = p + NWARPS;
            bool more = pn < NUNITS;
            float4 B0, B1, B2, B3;
            if (more) {
                const float4* nb = tbl + (size_t)pn * 128;
                B0 = __ldcs(nb + lane);           // prefetch next unit
                B1 = __ldcs(nb + 32 + lane);
                B2 = __ldcs(nb + 64 + lane);
                B3 = __ldcs(nb + 96 + lane);
            }
            // ---- row 0 of unit (A0,A1) ----
            float r0 = dot8(A0, A1, sM[lane],       sM[32 + lane]);
            float r1 = dot8(A0, A1, sM[64 + lane],  sM[96 + lane]);
            float r2 = dot8(A0, A1, sM[128 + lane], sM[160 + lane]);
#pragma unroll
            for (int o = 16; o; o >>= 1) {
                r0 += __shfl_xor_sync(0xffffffffu, r0, o);
                r1 += __shfl_xor_sync(0xffffffffu, r1, o);
                r2 += __shfl_xor_sync(0xffffffffu, r2, o);
            }
            // ---- row 1 of unit (A2,A3) ----
            float t0 = dot8(A2, A3, sM[lane],       sM[32 + lane]);
            float t1 = dot8(A2, A3, sM[64 + lane],  sM[96 + lane]);
            float t2 = dot8(A2, A3, sM[128 + lane], sM[160 + lane]);
#pragma unroll
            for (int o = 16; o; o >>= 1) {
                t0 += __shfl_xor_sync(0xffffffffu, t0, o);
                t1 += __shfl_xor_sync(0xffffffffu, t1, o);
                t2 += __shfl_xor_sync(0xffffffffu, t2, o);
            }
            if (lane < 2) {
                float4 v = (lane == 0) ? make_float4(r0, r1, r2, 0.f)
                                       : make_float4(t0, t1, t2, 0.f);
                g_P[2 * p + lane] = v;
            }
            if (!more) break;
            A0 = B0; A1 = B1; A2 = B2; A3 = B3;
            p = pn;
        }
    }

    grid_bar(2 * GRID);   // ---- barrier B: g_P / g_E ready ----

    // ================= Phase 2: gather + relu + emit ==================
    {
        int q = bid * 80 + tid;                 // 80 quads/block, coalesced
        if (tid < 80 && q < NSAMP / 4) {
            int i = q * 4;
            int c = i / (NB * NS);
            int b = (i - c * (NB * NS)) / NS;

            int4 sv = sampled[q];
            int  vb = c * BINS;
            float4 p0 = g_P[vb + sv.x];
            float4 p1 = g_P[vb + sv.y];
            float4 p2 = g_P[vb + sv.z];
            float4 p3 = g_P[vb + sv.w];
            float4 e  = g_E[b * N_CHROM + c];

            float4* o4 = reinterpret_cast<float4*>(out + 12 * (size_t)q);
            o4[0] = make_float4(fmaxf(p0.x + e.x, 0.f), fmaxf(p0.y + e.y, 0.f),
                                fmaxf(p0.z + e.z, 0.f), fmaxf(p1.x + e.x, 0.f));
            o4[1] = make_float4(fmaxf(p1.y + e.y, 0.f), fmaxf(p1.z + e.z, 0.f),
                                fmaxf(p2.x + e.x, 0.f), fmaxf(p2.y + e.y, 0.f));
            o4[2] = make_float4(fmaxf(p2.z + e.z, 0.f), fmaxf(p3.x + e.x, 0.f),
                                fmaxf(p3.y + e.y, 0.f), fmaxf(p3.z + e.z, 0.f));

            if (write_targets) {
                int4 tv = targets[q];
                reinterpret_cast<float4*>(out + 3 * NSAMP)[q] =
                    make_float4((float)tv.x, (float)tv.y, (float)tv.z, (float)tv.w);
            }
        }
    }

    // ---- final arrive: last arrival resets counter for graph replay ----
    __syncthreads();
    if (tid == 0) {
        unsigned prev = atomicAdd(&g_bar, 1u);
        if (prev + 1u == 3u * GRID) atomicExch(&g_bar, 0u);
    }
}

// ---------------------------------------------------------------------------
extern "C" void kernel_launch(void* const* d_in, const int* in_sizes, int n_in,
                              void* d_out, int out_size) {
    const float*  eos_emb = (const float*) d_in[0];
    const int4*   sampled = (const int4*)  d_in[1];
    const int4*   targets = (const int4*)  d_in[2];
    const float4* tbl     = (const float4*)d_in[3];
    const float*  Wbin    = (const float*) d_in[4];
    const float*  Weos    = (const float*) d_in[5];
    const float*  beos    = (const float*) d_in[6];
    const float*  Wfc     = (const float*) d_in[7];
    const float*  bfc     = (const float*) d_in[8];
    float* out = (float*)d_out;

    int write_targets = (out_size >= 4 * NSAMP) ? 1 : 0;
    k_fused<<<GRID, 256>>>(eos_emb, sampled, targets, tbl,
                           Wbin, Weos, beos, Wfc, bfc, out, write_targets);
}